// round 6
// baseline (speedup 1.0000x reference)
#include <cuda_runtime.h>
#include <math.h>

#define T 32
#define N 512
#define E 64
#define F 64
#define HD 64
#define SLOPE 0.2f

// ---------------- device scratch ----------------
__device__ float g_h[T * N * HD];       // 4 MB
__device__ float g_shyp[T * N];
__device__ float g_sind[T * N];
__device__ float g_emax[T * E];
__device__ float g_einv[T * E];
__device__ float g_ind[T * N * HD];     // 4 MB
__device__ int   g_adj_cnt[N];
__device__ int   g_adj_nbr[N * N];
__device__ int   g_ne_cnt[N];
__device__ int   g_ne_off[N];
__device__ int   g_ne_lst[N * E];
__device__ int   g_en_cnt[E];
__device__ int   g_en_lst[E * N];
__device__ int   g_wl_n[N * E];
__device__ int   g_wl_e[N * E];
__device__ int   g_nnz;
__device__ int   g_Mhyp;
__device__ int   g_Mtot;
__device__ float g_zall[T * N * E + T * N];

__device__ __forceinline__ float elu1(float v) { return v > 0.f ? v : expm1f(v); }

// ---------------- fused front: h-GEMM + all CSR builds + scan (block-specialized) ----------------
// blocks 0..511: h = x@W (32 rows each) + s_hyp/s_ind
// blocks 512..575: adjacency CSR (8 rows each)
// blocks 576..583: edge->node CSR (8 edges each)
// block 584: node->edge CSR + prefix scan + worklist (256 thr, 2 nodes each)
__global__ void __launch_bounds__(256) k_front(const float* __restrict__ x,
                                               const float* __restrict__ W,
                                               const float* __restrict__ ah,
                                               const float* __restrict__ ai,
                                               const int* __restrict__ adj,
                                               const int* __restrict__ Hm) {
    int b = blockIdx.x;
    int tid = threadIdx.x;
    int lane = tid & 31;
    int wrp = tid >> 5;

    if (b < 512) {
        __shared__ float xs[32][65];
        __shared__ float ws[64][65];
        int r0 = b * 32;

        for (int i = tid; i < 32 * 64; i += 256) {
            int r = i >> 6, c = i & 63;
            xs[r][c] = x[(r0 + r) * F + c];
        }
        for (int i = tid; i < 64 * 64; i += 256) {
            int r = i >> 6, c = i & 63;
            ws[r][c] = W[i];
        }
        __syncthreads();

        int ty = tid >> 4, tx = tid & 15;
        float acc[2][4] = {{0.f,0.f,0.f,0.f},{0.f,0.f,0.f,0.f}};
        #pragma unroll 8
        for (int k = 0; k < 64; k++) {
            float xr0 = xs[ty * 2 + 0][k];
            float xr1 = xs[ty * 2 + 1][k];
            float wv[4];
            #pragma unroll
            for (int j = 0; j < 4; j++) wv[j] = ws[k][tx * 4 + j];
            #pragma unroll
            for (int j = 0; j < 4; j++) {
                acc[0][j] = fmaf(xr0, wv[j], acc[0][j]);
                acc[1][j] = fmaf(xr1, wv[j], acc[1][j]);
            }
        }
        __syncthreads();
        #pragma unroll
        for (int i = 0; i < 2; i++) {
            int r = ty * 2 + i;
            #pragma unroll
            for (int j = 0; j < 4; j++) xs[r][tx * 4 + j] = acc[i][j];
            float4 v = make_float4(acc[i][0], acc[i][1], acc[i][2], acc[i][3]);
            *(float4*)&g_h[(r0 + r) * HD + tx * 4] = v;
        }
        __syncthreads();

        int row = tid >> 3, oct = tid & 7;
        float sh = 0.f, si = 0.f;
        #pragma unroll
        for (int k = 0; k < 8; k++) {
            float v = xs[row][oct * 8 + k];
            sh = fmaf(v, __ldg(&ah[oct * 8 + k]), sh);
            si = fmaf(v, __ldg(&ai[oct * 8 + k]), si);
        }
        #pragma unroll
        for (int o = 4; o > 0; o >>= 1) {
            sh += __shfl_xor_sync(0xffffffffu, sh, o);
            si += __shfl_xor_sync(0xffffffffu, si, o);
        }
        if (oct == 0) {
            g_shyp[r0 + row] = sh >= 0.f ? sh : SLOPE * sh;
            g_sind[r0 + row] = si >= 0.f ? si : SLOPE * si;
        }
    } else if (b < 576) {                      // adjacency CSR
        int i = (b - 512) * 8 + wrp;
        int cnt = 0;
        #pragma unroll
        for (int c = 0; c < N / 32; c++) {
            int j = c * 32 + lane;
            bool m = adj[i * N + j] != 0;
            unsigned bl = __ballot_sync(0xffffffffu, m);
            if (m) g_adj_nbr[i * N + cnt + __popc(bl & ((1u << lane) - 1u))] = j;
            cnt += __popc(bl);
        }
        if (lane == 0) g_adj_cnt[i] = cnt;
    } else if (b < 584) {                      // edge -> member nodes
        int e = (b - 576) * 8 + wrp;
        int cnt = 0;
        #pragma unroll
        for (int c = 0; c < N / 32; c++) {
            int n = c * 32 + lane;
            bool m = Hm[n * E + e] != 0;
            unsigned bl = __ballot_sync(0xffffffffu, m);
            if (m) g_en_lst[e * N + cnt + __popc(bl & ((1u << lane) - 1u))] = n;
            cnt += __popc(bl);
        }
        if (lane == 0) g_en_cnt[e] = cnt;
    } else {                                   // node->edge CSR + scan + worklist
        __shared__ int buf[256];
        int n0 = tid * 2, n1 = tid * 2 + 1;
        int c0 = 0, c1 = 0;
        #pragma unroll
        for (int e = 0; e < E; e++) {
            if (Hm[n0 * E + e] != 0) g_ne_lst[n0 * E + (c0++)] = e;
            if (Hm[n1 * E + e] != 0) g_ne_lst[n1 * E + (c1++)] = e;
        }
        g_ne_cnt[n0] = c0;
        g_ne_cnt[n1] = c1;
        buf[tid] = c0 + c1;
        __syncthreads();
        #pragma unroll
        for (int o = 1; o < 256; o <<= 1) {
            int add = (tid >= o) ? buf[tid - o] : 0;
            __syncthreads();
            buf[tid] += add;
            __syncthreads();
        }
        int S = buf[tid];
        int off0 = S - c0 - c1;
        int off1 = off0 + c0;
        g_ne_off[n0] = off0;
        g_ne_off[n1] = off1;
        if (tid == 255) {
            int nnz = S;
            g_nnz = nnz;
            g_Mhyp = T * nnz;
            g_Mtot = T * nnz + T * N;
        }
        for (int j = 0; j < c0; j++) {
            g_wl_n[off0 + j] = n0;
            g_wl_e[off0 + j] = g_ne_lst[n0 * E + j];
        }
        for (int j = 0; j < c1; j++) {
            g_wl_n[off1 + j] = n1;
            g_wl_e[off1 + j] = g_ne_lst[n1 * E + j];
        }
    }
}

// ---------------- fused: industry (warp-per-row, float2 lanes) + hyperedge stats ----------------
__global__ void __launch_bounds__(256) k_mid() {
    int b = blockIdx.x;
    int tid = threadIdx.x;
    int lane = tid & 31;
    int wrp = tid >> 5;
    if (b < 2048) {
        __shared__ float smw[8][512];
        int row = b * 8 + wrp;
        int t = row >> 9;
        int i = row & (N - 1);
        int deg = g_adj_cnt[i];
        const int* nbr = g_adj_nbr + i * N;
        const float* si = g_sind + t * N;

        float m = -3.0e38f;
        for (int k = lane; k < deg; k += 32) m = fmaxf(m, si[nbr[k]]);
        #pragma unroll
        for (int o = 16; o > 0; o >>= 1) m = fmaxf(m, __shfl_xor_sync(0xffffffffu, m, o));
        float s = 0.f;
        for (int k = lane; k < deg; k += 32) {
            float w = expf(si[nbr[k]] - m);
            smw[wrp][k] = w;
            s += w;
        }
        #pragma unroll
        for (int o = 16; o > 0; o >>= 1) s += __shfl_xor_sync(0xffffffffu, s, o);
        float inv = 1.f / s;
        __syncwarp();

        const float* hb = g_h + t * N * HD;
        float2 a0 = {0.f,0.f}, a1 = {0.f,0.f}, a2 = {0.f,0.f}, a3 = {0.f,0.f};
        int k = 0;
        for (; k + 4 <= deg; k += 4) {
            float w0 = smw[wrp][k],     w1 = smw[wrp][k + 1];
            float w2 = smw[wrp][k + 2], w3 = smw[wrp][k + 3];
            float2 h0 = *(const float2*)&hb[nbr[k]     * HD + lane * 2];
            float2 h1 = *(const float2*)&hb[nbr[k + 1] * HD + lane * 2];
            float2 h2 = *(const float2*)&hb[nbr[k + 2] * HD + lane * 2];
            float2 h3 = *(const float2*)&hb[nbr[k + 3] * HD + lane * 2];
            a0.x = fmaf(w0, h0.x, a0.x); a0.y = fmaf(w0, h0.y, a0.y);
            a1.x = fmaf(w1, h1.x, a1.x); a1.y = fmaf(w1, h1.y, a1.y);
            a2.x = fmaf(w2, h2.x, a2.x); a2.y = fmaf(w2, h2.y, a2.y);
            a3.x = fmaf(w3, h3.x, a3.x); a3.y = fmaf(w3, h3.y, a3.y);
        }
        for (; k < deg; k++) {
            float w0 = smw[wrp][k];
            float2 h0 = *(const float2*)&hb[nbr[k] * HD + lane * 2];
            a0.x = fmaf(w0, h0.x, a0.x); a0.y = fmaf(w0, h0.y, a0.y);
        }
        float2 r;
        r.x = ((a0.x + a1.x) + (a2.x + a3.x)) * inv;
        r.y = ((a0.y + a1.y) + (a2.y + a3.y)) * inv;
        *(float2*)&g_ind[row * HD + lane * 2] = r;
    } else {
        int w = (b - 2048) * 8 + wrp;
        int t = w / E, e = w % E;
        int cnt = g_en_cnt[e];
        const int* lst = g_en_lst + e * N;
        const float* sh = g_shyp + t * N;
        float m = -3.0e38f;
        for (int i = lane; i < cnt; i += 32) m = fmaxf(m, sh[lst[i]]);
        #pragma unroll
        for (int o = 16; o > 0; o >>= 1) m = fmaxf(m, __shfl_xor_sync(0xffffffffu, m, o));
        float s = 0.f;
        for (int i = lane; i < cnt; i += 32) s += expf(sh[lst[i]] - m);
        #pragma unroll
        for (int o = 16; o > 0; o >>= 1) s += __shfl_xor_sync(0xffffffffu, s, o);
        if (lane == 0) { g_emax[w] = m; g_einv[w] = 1.f / s; }
    }
}

// ---------------- phase A: 128-row tiles, 256 threads, 8x4 register tiles ----------------
__global__ void __launch_bounds__(256) k_scoreA(const float* __restrict__ Wc1g,
                                                const float* __restrict__ bc1g,
                                                const float* __restrict__ wc2g,
                                                const float* __restrict__ bc2g) {
    __shared__ float Ws[HD * HD];              // 16 KB
    __shared__ float fsT[HD * 128];            // 32 KB, [k][row]
    int tid = threadIdx.x;
    int tx = tid & 15, ty = tid >> 4;          // GEMM: 4 cols, 8 rows per thread
    int r = tid & 127, half = tid >> 7;        // fill: 2 threads per row, 32 dims each

    for (int i = tid; i < HD * HD; i += 256) Ws[i] = Wc1g[i];
    float bc1r[4], wc2r[4];
    #pragma unroll
    for (int j = 0; j < 4; j++) {
        bc1r[j] = __ldg(&bc1g[tx * 4 + j]);
        wc2r[j] = __ldg(&wc2g[tx * 4 + j]);
    }
    float bc2 = __ldg(&bc2g[0]);
    int Mtot = g_Mtot, Mhyp = g_Mhyp, nnz = g_nnz;
    int ntiles = (Mtot + 127) >> 7;

    for (int tile = blockIdx.x; tile < ntiles; tile += gridDim.x) {
        __syncthreads();
        int row = tile * 128 + r;
        int kb = half * 32;
        if (row < Mhyp) {
            int t = row / nnz;
            int idx = row - t * nnz;
            int n = g_wl_n[idx], e = g_wl_e[idx];
            float a = expf(g_shyp[t * N + n] - g_emax[t * E + e]) * g_einv[t * E + e];
            const float4* hp = (const float4*)&g_h[(t * N + n) * HD + kb];
            #pragma unroll
            for (int q = 0; q < 8; q++) {
                float4 v = hp[q];
                fsT[(kb + q * 4 + 0) * 128 + r] = elu1(a * v.x);
                fsT[(kb + q * 4 + 1) * 128 + r] = elu1(a * v.y);
                fsT[(kb + q * 4 + 2) * 128 + r] = elu1(a * v.z);
                fsT[(kb + q * 4 + 3) * 128 + r] = elu1(a * v.w);
            }
        } else if (row < Mtot) {
            const float4* ip = (const float4*)&g_ind[(row - Mhyp) * HD + kb];
            #pragma unroll
            for (int q = 0; q < 8; q++) {
                float4 v = ip[q];
                fsT[(kb + q * 4 + 0) * 128 + r] = v.x;
                fsT[(kb + q * 4 + 1) * 128 + r] = v.y;
                fsT[(kb + q * 4 + 2) * 128 + r] = v.z;
                fsT[(kb + q * 4 + 3) * 128 + r] = v.w;
            }
        } else {
            #pragma unroll
            for (int q = 0; q < 32; q++) fsT[(kb + q) * 128 + r] = 0.f;
        }
        __syncthreads();

        float acc[8][4];
        #pragma unroll
        for (int i = 0; i < 8; i++)
            #pragma unroll
            for (int j = 0; j < 4; j++) acc[i][j] = 0.f;

        #pragma unroll 8
        for (int k = 0; k < HD; k++) {
            float4 f0 = *(const float4*)&fsT[k * 128 + ty * 8];
            float4 f1 = *(const float4*)&fsT[k * 128 + ty * 8 + 4];
            float4 w = *(const float4*)&Ws[k * HD + tx * 4];
            float fv[8] = {f0.x, f0.y, f0.z, f0.w, f1.x, f1.y, f1.z, f1.w};
            float wv[4] = {w.x, w.y, w.z, w.w};
            #pragma unroll
            for (int i = 0; i < 8; i++)
                #pragma unroll
                for (int j = 0; j < 4; j++)
                    acc[i][j] = fmaf(fv[i], wv[j], acc[i][j]);
        }

        int rb = tile * 128 + ty * 8;
        #pragma unroll
        for (int i = 0; i < 8; i++) {
            float p = 0.f;
            #pragma unroll
            for (int j = 0; j < 4; j++)
                p = fmaf(fmaxf(acc[i][j] + bc1r[j], 0.f), wc2r[j], p);
            p += __shfl_down_sync(0xffffffffu, p, 8, 16);
            p += __shfl_down_sync(0xffffffffu, p, 4, 16);
            p += __shfl_down_sync(0xffffffffu, p, 2, 16);
            p += __shfl_down_sync(0xffffffffu, p, 1, 16);
            if (tx == 0 && rb + i < Mtot) g_zall[rb + i] = p + bc2;
        }
    }
}

// ---------------- phase B: y8 build (4 thr/row) + score + final combine ----------------
#define SCORE_GEMM_Z(ZSTORE)                                                     \
    {                                                                            \
        float acc[4][4];                                                         \
        _Pragma("unroll")                                                        \
        for (int i = 0; i < 4; i++)                                              \
            _Pragma("unroll")                                                    \
            for (int j = 0; j < 4; j++) acc[i][j] = 0.f;                         \
        _Pragma("unroll 16")                                                     \
        for (int k = 0; k < HD; k++) {                                           \
            float4 f = *(const float4*)&fsT[k * 64 + ty4 * 4];                   \
            float4 w = *(const float4*)&Ws[k * HD + tx * 4];                     \
            float fv[4] = {f.x, f.y, f.z, f.w};                                  \
            float wv[4] = {w.x, w.y, w.z, w.w};                                  \
            _Pragma("unroll")                                                    \
            for (int i = 0; i < 4; i++)                                          \
                _Pragma("unroll")                                                \
                for (int j = 0; j < 4; j++)                                      \
                    acc[i][j] = fmaf(fv[i], wv[j], acc[i][j]);                   \
        }                                                                        \
        _Pragma("unroll")                                                        \
        for (int i = 0; i < 4; i++) {                                            \
            float p = 0.f;                                                       \
            _Pragma("unroll")                                                    \
            for (int j = 0; j < 4; j++)                                          \
                p = fmaf(fmaxf(acc[i][j] + bc1r[j], 0.f), wc2r[j], p);           \
            p += __shfl_down_sync(0xffffffffu, p, 8, 16);                        \
            p += __shfl_down_sync(0xffffffffu, p, 4, 16);                        \
            p += __shfl_down_sync(0xffffffffu, p, 2, 16);                        \
            p += __shfl_down_sync(0xffffffffu, p, 1, 16);                        \
            p += bc2;                                                            \
            if (tx == 0) { ZSTORE; }                                             \
        }                                                                        \
    }

__global__ void __launch_bounds__(256) k_scoreBfin(float* __restrict__ out,
                                                   const float* __restrict__ Wc1g,
                                                   const float* __restrict__ bc1g,
                                                   const float* __restrict__ wc2g,
                                                   const float* __restrict__ bc2g) {
    __shared__ float Ws[HD * HD];
    __shared__ float fsT[HD * 64];
    __shared__ float zs[64];
    int tid = threadIdx.x;
    int tx = tid & 15, ty4 = tid >> 4;
    int r = tid & 63, dgrp = tid >> 6;

    for (int i = tid; i < HD * HD; i += 256) Ws[i] = Wc1g[i];
    float bc1r[4], wc2r[4];
    #pragma unroll
    for (int j = 0; j < 4; j++) {
        bc1r[j] = __ldg(&bc1g[tx * 4 + j]);
        wc2r[j] = __ldg(&wc2g[tx * 4 + j]);
    }
    float bc2 = __ldg(&bc2g[0]);
    int Mhyp = g_Mhyp, nnz = g_nnz;

    int row = blockIdx.x * 64 + r;
    int t = row >> 9, n = row & (N - 1);
    int deg = g_ne_cnt[n];
    int off = g_ne_off[n];

    {
        float h16[16];
        const float4* hp = (const float4*)&g_h[row * HD + dgrp * 16];
        #pragma unroll
        for (int q = 0; q < 4; q++) {
            float4 v = hp[q];
            h16[q * 4 + 0] = v.x; h16[q * 4 + 1] = v.y;
            h16[q * 4 + 2] = v.z; h16[q * 4 + 3] = v.w;
        }
        float shn = g_shyp[row];
        const float* zb = g_zall + t * nnz + off;
        const int* el = g_ne_lst + n * E;
        float M = -3.0e38f;
        for (int j = 0; j < deg; j++) M = fmaxf(M, zb[j]);
        float y[16];
        #pragma unroll
        for (int q = 0; q < 16; q++) y[q] = 0.f;
        float S = 0.f;
        for (int j = 0; j < deg; j++) {
            float w = expf(zb[j] - M);
            S += w;
            int e = el[j];
            float a = expf(shn - g_emax[t * E + e]) * g_einv[t * E + e];
            #pragma unroll
            for (int q = 0; q < 16; q++)
                y[q] = fmaf(w, elu1(a * h16[q]), y[q]);
        }
        float inv = 1.f / S;
        #pragma unroll
        for (int q = 0; q < 16; q++)
            fsT[(dgrp * 16 + q) * 64 + r] = y[q] * inv;
    }
    __syncthreads();

    SCORE_GEMM_Z(zs[ty4 * 4 + i] = p);
    __syncthreads();

    float z2 = zs[r];
    float z1 = g_zall[Mhyp + row];
    float m2 = fmaxf(z1, z2);
    float w1 = expf(z1 - m2), w2 = expf(z2 - m2);
    float inv = 1.f / (w1 + w2);
    const float4* ip = (const float4*)&g_ind[row * HD + dgrp * 16];
    float4* op = (float4*)&out[row * HD + dgrp * 16];
    #pragma unroll
    for (int q = 0; q < 4; q++) {
        float4 iv = ip[q];
        float4 rr;
        rr.x = (w1 * iv.x + w2 * fsT[(dgrp * 16 + q * 4 + 0) * 64 + r]) * inv;
        rr.y = (w1 * iv.y + w2 * fsT[(dgrp * 16 + q * 4 + 1) * 64 + r]) * inv;
        rr.z = (w1 * iv.z + w2 * fsT[(dgrp * 16 + q * 4 + 2) * 64 + r]) * inv;
        rr.w = (w1 * iv.w + w2 * fsT[(dgrp * 16 + q * 4 + 3) * 64 + r]) * inv;
        op[q] = rr;
    }
}

// ---------------- launch ----------------
extern "C" void kernel_launch(void* const* d_in, const int* in_sizes, int n_in,
                              void* d_out, int out_size) {
    int off = (n_in >= 11) ? 1 : 0;
    const float* x   = (const float*)d_in[0];
    const int*   Hm  = (const int*)d_in[1];
    const int*   adj = (const int*)d_in[2];
    const float* W   = (const float*)d_in[3 + off];
    const float* ah  = (const float*)d_in[4 + off];
    const float* ai  = (const float*)d_in[5 + off];
    const float* Wc1 = (const float*)d_in[6 + off];
    const float* bc1 = (const float*)d_in[7 + off];
    const float* wc2 = (const float*)d_in[8 + off];
    const float* bc2 = (const float*)d_in[9 + off];
    float* outp = (float*)d_out;

    k_front<<<585, 256>>>(x, W, ah, ai, adj, Hm);
    k_mid<<<2048 + 256, 256>>>();
    k_scoreA<<<512, 256>>>(Wc1, bc1, wc2, bc2);
    k_scoreBfin<<<T * N / 64, 256>>>(outp, Wc1, bc1, wc2, bc2);
}

// round 7
// speedup vs baseline: 1.0411x; 1.0411x over previous
#include <cuda_runtime.h>
#include <math.h>

#define T 32
#define N 512
#define E 64
#define F 64
#define HD 64
#define SLOPE 0.2f

// ---------------- device scratch ----------------
__device__ float g_h[T * N * HD];       // 4 MB
__device__ float g_shyp[T * N];
__device__ float g_sind[T * N];
__device__ float g_emax[T * E];
__device__ float g_einv[T * E];
__device__ float g_ind[T * N * HD];     // 4 MB
__device__ int   g_adj_cnt[N];
__device__ int   g_adj_nbr[N * N];
__device__ int   g_ne_cnt[N];
__device__ int   g_ne_off[N];
__device__ int   g_ne_lst[N * E];
__device__ int   g_en_cnt[E];
__device__ int   g_en_lst[E * N];
__device__ int   g_wl_n[N * E];
__device__ int   g_wl_e[N * E];
__device__ int   g_nnz;
__device__ int   g_Mhyp;
__device__ int   g_Mtot;
__device__ float g_zall[T * N * E + T * N];

__device__ __forceinline__ float elu1(float v) { return v > 0.f ? v : expm1f(v); }

// ---------------- fused front: h-GEMM + all CSR builds + scan (block-specialized) ----------------
__global__ void __launch_bounds__(256) k_front(const float* __restrict__ x,
                                               const float* __restrict__ W,
                                               const float* __restrict__ ah,
                                               const float* __restrict__ ai,
                                               const int* __restrict__ adj,
                                               const int* __restrict__ Hm) {
    int b = blockIdx.x;
    int tid = threadIdx.x;
    int lane = tid & 31;
    int wrp = tid >> 5;

    if (b < 512) {
        __shared__ float xs[32][65];
        __shared__ float ws[64][65];
        int r0 = b * 32;

        for (int i = tid; i < 32 * 64; i += 256) {
            int r = i >> 6, c = i & 63;
            xs[r][c] = x[(r0 + r) * F + c];
        }
        for (int i = tid; i < 64 * 64; i += 256) {
            int r = i >> 6, c = i & 63;
            ws[r][c] = W[i];
        }
        __syncthreads();

        int ty = tid >> 4, tx = tid & 15;
        float acc[2][4] = {{0.f,0.f,0.f,0.f},{0.f,0.f,0.f,0.f}};
        #pragma unroll 8
        for (int k = 0; k < 64; k++) {
            float xr0 = xs[ty * 2 + 0][k];
            float xr1 = xs[ty * 2 + 1][k];
            float wv[4];
            #pragma unroll
            for (int j = 0; j < 4; j++) wv[j] = ws[k][tx * 4 + j];
            #pragma unroll
            for (int j = 0; j < 4; j++) {
                acc[0][j] = fmaf(xr0, wv[j], acc[0][j]);
                acc[1][j] = fmaf(xr1, wv[j], acc[1][j]);
            }
        }
        __syncthreads();
        #pragma unroll
        for (int i = 0; i < 2; i++) {
            int r = ty * 2 + i;
            #pragma unroll
            for (int j = 0; j < 4; j++) xs[r][tx * 4 + j] = acc[i][j];
            float4 v = make_float4(acc[i][0], acc[i][1], acc[i][2], acc[i][3]);
            *(float4*)&g_h[(r0 + r) * HD + tx * 4] = v;
        }
        __syncthreads();

        int row = tid >> 3, oct = tid & 7;
        float sh = 0.f, si = 0.f;
        #pragma unroll
        for (int k = 0; k < 8; k++) {
            float v = xs[row][oct * 8 + k];
            sh = fmaf(v, __ldg(&ah[oct * 8 + k]), sh);
            si = fmaf(v, __ldg(&ai[oct * 8 + k]), si);
        }
        #pragma unroll
        for (int o = 4; o > 0; o >>= 1) {
            sh += __shfl_xor_sync(0xffffffffu, sh, o);
            si += __shfl_xor_sync(0xffffffffu, si, o);
        }
        if (oct == 0) {
            g_shyp[r0 + row] = sh >= 0.f ? sh : SLOPE * sh;
            g_sind[r0 + row] = si >= 0.f ? si : SLOPE * si;
        }
    } else if (b < 576) {                      // adjacency CSR
        int i = (b - 512) * 8 + wrp;
        int cnt = 0;
        #pragma unroll
        for (int c = 0; c < N / 32; c++) {
            int j = c * 32 + lane;
            bool m = adj[i * N + j] != 0;
            unsigned bl = __ballot_sync(0xffffffffu, m);
            if (m) g_adj_nbr[i * N + cnt + __popc(bl & ((1u << lane) - 1u))] = j;
            cnt += __popc(bl);
        }
        if (lane == 0) g_adj_cnt[i] = cnt;
    } else if (b < 584) {                      // edge -> member nodes
        int e = (b - 576) * 8 + wrp;
        int cnt = 0;
        #pragma unroll
        for (int c = 0; c < N / 32; c++) {
            int n = c * 32 + lane;
            bool m = Hm[n * E + e] != 0;
            unsigned bl = __ballot_sync(0xffffffffu, m);
            if (m) g_en_lst[e * N + cnt + __popc(bl & ((1u << lane) - 1u))] = n;
            cnt += __popc(bl);
        }
        if (lane == 0) g_en_cnt[e] = cnt;
    } else {                                   // node->edge CSR + scan + worklist
        __shared__ int buf[256];
        int n0 = tid * 2, n1 = tid * 2 + 1;
        int c0 = 0, c1 = 0;
        #pragma unroll
        for (int e = 0; e < E; e++) {
            if (Hm[n0 * E + e] != 0) g_ne_lst[n0 * E + (c0++)] = e;
            if (Hm[n1 * E + e] != 0) g_ne_lst[n1 * E + (c1++)] = e;
        }
        g_ne_cnt[n0] = c0;
        g_ne_cnt[n1] = c1;
        buf[tid] = c0 + c1;
        __syncthreads();
        #pragma unroll
        for (int o = 1; o < 256; o <<= 1) {
            int add = (tid >= o) ? buf[tid - o] : 0;
            __syncthreads();
            buf[tid] += add;
            __syncthreads();
        }
        int S = buf[tid];
        int off0 = S - c0 - c1;
        int off1 = off0 + c0;
        g_ne_off[n0] = off0;
        g_ne_off[n1] = off1;
        if (tid == 255) {
            int nnz = S;
            g_nnz = nnz;
            g_Mhyp = T * nnz;
            g_Mtot = T * nnz + T * N;
        }
        for (int j = 0; j < c0; j++) {
            g_wl_n[off0 + j] = n0;
            g_wl_e[off0 + j] = g_ne_lst[n0 * E + j];
        }
        for (int j = 0; j < c1; j++) {
            g_wl_n[off1 + j] = n1;
            g_wl_e[off1 + j] = g_ne_lst[n1 * E + j];
        }
    }
}

// ---------------- fused: industry (warp-per-row, 8-wide MLP) + hyperedge stats ----------------
__global__ void __launch_bounds__(256) k_mid() {
    int b = blockIdx.x;
    int tid = threadIdx.x;
    int lane = tid & 31;
    int wrp = tid >> 5;
    if (b < 2048) {
        __shared__ float smw[8][512];
        int row = b * 8 + wrp;
        int t = row >> 9;
        int i = row & (N - 1);
        int deg = g_adj_cnt[i];
        const int* nbr = g_adj_nbr + i * N;
        const float* si = g_sind + t * N;

        float m = -3.0e38f;
        for (int k = lane; k < deg; k += 32) m = fmaxf(m, si[nbr[k]]);
        #pragma unroll
        for (int o = 16; o > 0; o >>= 1) m = fmaxf(m, __shfl_xor_sync(0xffffffffu, m, o));
        float s = 0.f;
        for (int k = lane; k < deg; k += 32) {
            float w = expf(si[nbr[k]] - m);
            smw[wrp][k] = w;
            s += w;
        }
        #pragma unroll
        for (int o = 16; o > 0; o >>= 1) s += __shfl_xor_sync(0xffffffffu, s, o);
        float inv = 1.f / s;
        __syncwarp();

        const float* hb = g_h + t * N * HD;
        float2 ac[8];
        #pragma unroll
        for (int u = 0; u < 8; u++) ac[u] = make_float2(0.f, 0.f);
        int k = 0;
        for (; k + 8 <= deg; k += 8) {
            #pragma unroll
            for (int u = 0; u < 8; u++) {
                float w = smw[wrp][k + u];
                float2 hv = *(const float2*)&hb[nbr[k + u] * HD + lane * 2];
                ac[u].x = fmaf(w, hv.x, ac[u].x);
                ac[u].y = fmaf(w, hv.y, ac[u].y);
            }
        }
        for (; k < deg; k++) {
            float w = smw[wrp][k];
            float2 hv = *(const float2*)&hb[nbr[k] * HD + lane * 2];
            ac[0].x = fmaf(w, hv.x, ac[0].x);
            ac[0].y = fmaf(w, hv.y, ac[0].y);
        }
        float2 r;
        r.x = (((ac[0].x + ac[1].x) + (ac[2].x + ac[3].x)) +
               ((ac[4].x + ac[5].x) + (ac[6].x + ac[7].x))) * inv;
        r.y = (((ac[0].y + ac[1].y) + (ac[2].y + ac[3].y)) +
               ((ac[4].y + ac[5].y) + (ac[6].y + ac[7].y))) * inv;
        *(float2*)&g_ind[row * HD + lane * 2] = r;
    } else {
        int w = (b - 2048) * 8 + wrp;
        int t = w / E, e = w % E;
        int cnt = g_en_cnt[e];
        const int* lst = g_en_lst + e * N;
        const float* sh = g_shyp + t * N;
        float m = -3.0e38f;
        for (int i = lane; i < cnt; i += 32) m = fmaxf(m, sh[lst[i]]);
        #pragma unroll
        for (int o = 16; o > 0; o >>= 1) m = fmaxf(m, __shfl_xor_sync(0xffffffffu, m, o));
        float s = 0.f;
        for (int i = lane; i < cnt; i += 32) s += expf(sh[lst[i]] - m);
        #pragma unroll
        for (int o = 16; o > 0; o >>= 1) s += __shfl_xor_sync(0xffffffffu, s, o);
        if (lane == 0) { g_emax[w] = m; g_einv[w] = 1.f / s; }
    }
}

// ---------------- phase A: 128-row tiles, 256 threads, 8x4 register tiles ----------------
__global__ void __launch_bounds__(256) k_scoreA(const float* __restrict__ Wc1g,
                                                const float* __restrict__ bc1g,
                                                const float* __restrict__ wc2g,
                                                const float* __restrict__ bc2g) {
    __shared__ float Ws[HD * HD];              // 16 KB
    __shared__ float fsT[HD * 128];            // 32 KB, [k][row]
    int tid = threadIdx.x;
    int tx = tid & 15, ty = tid >> 4;
    int r = tid & 127, half = tid >> 7;

    for (int i = tid; i < HD * HD; i += 256) Ws[i] = Wc1g[i];
    float bc1r[4], wc2r[4];
    #pragma unroll
    for (int j = 0; j < 4; j++) {
        bc1r[j] = __ldg(&bc1g[tx * 4 + j]);
        wc2r[j] = __ldg(&wc2g[tx * 4 + j]);
    }
    float bc2 = __ldg(&bc2g[0]);
    int Mtot = g_Mtot, Mhyp = g_Mhyp, nnz = g_nnz;
    int ntiles = (Mtot + 127) >> 7;

    for (int tile = blockIdx.x; tile < ntiles; tile += gridDim.x) {
        __syncthreads();
        int row = tile * 128 + r;
        int kb = half * 32;
        if (row < Mhyp) {
            int t = row / nnz;
            int idx = row - t * nnz;
            int n = g_wl_n[idx], e = g_wl_e[idx];
            float a = expf(g_shyp[t * N + n] - g_emax[t * E + e]) * g_einv[t * E + e];
            const float4* hp = (const float4*)&g_h[(t * N + n) * HD + kb];
            #pragma unroll
            for (int q = 0; q < 8; q++) {
                float4 v = hp[q];
                fsT[(kb + q * 4 + 0) * 128 + r] = elu1(a * v.x);
                fsT[(kb + q * 4 + 1) * 128 + r] = elu1(a * v.y);
                fsT[(kb + q * 4 + 2) * 128 + r] = elu1(a * v.z);
                fsT[(kb + q * 4 + 3) * 128 + r] = elu1(a * v.w);
            }
        } else if (row < Mtot) {
            const float4* ip = (const float4*)&g_ind[(row - Mhyp) * HD + kb];
            #pragma unroll
            for (int q = 0; q < 8; q++) {
                float4 v = ip[q];
                fsT[(kb + q * 4 + 0) * 128 + r] = v.x;
                fsT[(kb + q * 4 + 1) * 128 + r] = v.y;
                fsT[(kb + q * 4 + 2) * 128 + r] = v.z;
                fsT[(kb + q * 4 + 3) * 128 + r] = v.w;
            }
        } else {
            #pragma unroll
            for (int q = 0; q < 32; q++) fsT[(kb + q) * 128 + r] = 0.f;
        }
        __syncthreads();

        float acc[8][4];
        #pragma unroll
        for (int i = 0; i < 8; i++)
            #pragma unroll
            for (int j = 0; j < 4; j++) acc[i][j] = 0.f;

        #pragma unroll 8
        for (int k = 0; k < HD; k++) {
            float4 f0 = *(const float4*)&fsT[k * 128 + ty * 8];
            float4 f1 = *(const float4*)&fsT[k * 128 + ty * 8 + 4];
            float4 w = *(const float4*)&Ws[k * HD + tx * 4];
            float fv[8] = {f0.x, f0.y, f0.z, f0.w, f1.x, f1.y, f1.z, f1.w};
            float wv[4] = {w.x, w.y, w.z, w.w};
            #pragma unroll
            for (int i = 0; i < 8; i++)
                #pragma unroll
                for (int j = 0; j < 4; j++)
                    acc[i][j] = fmaf(fv[i], wv[j], acc[i][j]);
        }

        int rb = tile * 128 + ty * 8;
        #pragma unroll
        for (int i = 0; i < 8; i++) {
            float p = 0.f;
            #pragma unroll
            for (int j = 0; j < 4; j++)
                p = fmaf(fmaxf(acc[i][j] + bc1r[j], 0.f), wc2r[j], p);
            p += __shfl_down_sync(0xffffffffu, p, 8, 16);
            p += __shfl_down_sync(0xffffffffu, p, 4, 16);
            p += __shfl_down_sync(0xffffffffu, p, 2, 16);
            p += __shfl_down_sync(0xffffffffu, p, 1, 16);
            if (tx == 0 && rb + i < Mtot) g_zall[rb + i] = p + bc2;
        }
    }
}

// ---------------- phase B: 32-row tiles (grid 512), y8 build 8 thr/row + score + combine ----------------
__global__ void __launch_bounds__(256) k_scoreBfin(float* __restrict__ out,
                                                   const float* __restrict__ Wc1g,
                                                   const float* __restrict__ bc1g,
                                                   const float* __restrict__ wc2g,
                                                   const float* __restrict__ bc2g) {
    __shared__ float Ws[HD * HD];              // 16 KB
    __shared__ float fsT[HD * 32];             // 8 KB, [k][row]
    __shared__ float zs[32];
    int tid = threadIdx.x;
    int tx = tid & 15, ty = tid >> 4;          // GEMM: 4 cols x 2 rows
    int r = tid & 31, dgrp = tid >> 5;         // fill/combine: 8 thr per row, 8 dims each

    for (int i = tid; i < HD * HD; i += 256) Ws[i] = Wc1g[i];
    float bc1r[4], wc2r[4];
    #pragma unroll
    for (int j = 0; j < 4; j++) {
        bc1r[j] = __ldg(&bc1g[tx * 4 + j]);
        wc2r[j] = __ldg(&wc2g[tx * 4 + j]);
    }
    float bc2 = __ldg(&bc2g[0]);
    int Mhyp = g_Mhyp, nnz = g_nnz;

    int row = blockIdx.x * 32 + r;             // (t,n)
    int t = row >> 9, n = row & (N - 1);
    int deg = g_ne_cnt[n];
    int off = g_ne_off[n];
    int kb = dgrp * 8;

    // phase 1: y8 for 8 dims of this row
    {
        float h8[8];
        const float4* hp = (const float4*)&g_h[row * HD + kb];
        float4 v0 = hp[0], v1 = hp[1];
        h8[0] = v0.x; h8[1] = v0.y; h8[2] = v0.z; h8[3] = v0.w;
        h8[4] = v1.x; h8[5] = v1.y; h8[6] = v1.z; h8[7] = v1.w;
        float shn = g_shyp[row];
        const float* zb = g_zall + t * nnz + off;
        const int* el = g_ne_lst + n * E;
        float M = -3.0e38f;
        for (int j = 0; j < deg; j++) M = fmaxf(M, zb[j]);
        float y[8];
        #pragma unroll
        for (int q = 0; q < 8; q++) y[q] = 0.f;
        float S = 0.f;
        for (int j = 0; j < deg; j++) {
            float w = expf(zb[j] - M);
            S += w;
            int e = el[j];
            float a = expf(shn - g_emax[t * E + e]) * g_einv[t * E + e];
            #pragma unroll
            for (int q = 0; q < 8; q++)
                y[q] = fmaf(w, elu1(a * h8[q]), y[q]);
        }
        float inv = 1.f / S;
        #pragma unroll
        for (int q = 0; q < 8; q++)
            fsT[(kb + q) * 32 + r] = y[q] * inv;
    }
    __syncthreads();

    // phase 2: GEMM 32x64 + z
    {
        float acc[2][4];
        #pragma unroll
        for (int i = 0; i < 2; i++)
            #pragma unroll
            for (int j = 0; j < 4; j++) acc[i][j] = 0.f;
        #pragma unroll 16
        for (int k = 0; k < HD; k++) {
            float2 f = *(const float2*)&fsT[k * 32 + ty * 2];
            float4 w = *(const float4*)&Ws[k * HD + tx * 4];
            float wv[4] = {w.x, w.y, w.z, w.w};
            #pragma unroll
            for (int j = 0; j < 4; j++) {
                acc[0][j] = fmaf(f.x, wv[j], acc[0][j]);
                acc[1][j] = fmaf(f.y, wv[j], acc[1][j]);
            }
        }
        #pragma unroll
        for (int i = 0; i < 2; i++) {
            float p = 0.f;
            #pragma unroll
            for (int j = 0; j < 4; j++)
                p = fmaf(fmaxf(acc[i][j] + bc1r[j], 0.f), wc2r[j], p);
            p += __shfl_down_sync(0xffffffffu, p, 8, 16);
            p += __shfl_down_sync(0xffffffffu, p, 4, 16);
            p += __shfl_down_sync(0xffffffffu, p, 2, 16);
            p += __shfl_down_sync(0xffffffffu, p, 1, 16);
            if (tx == 0) zs[ty * 2 + i] = p + bc2;
        }
    }
    __syncthreads();

    // phase 3: combine, 8 thr per row, 8 dims each
    float z2 = zs[r];
    float z1 = g_zall[Mhyp + row];
    float m2 = fmaxf(z1, z2);
    float w1 = expf(z1 - m2), w2 = expf(z2 - m2);
    float inv = 1.f / (w1 + w2);
    const float4* ip = (const float4*)&g_ind[row * HD + kb];
    float4* op = (float4*)&out[row * HD + kb];
    #pragma unroll
    for (int q = 0; q < 2; q++) {
        float4 iv = ip[q];
        float4 rr;
        rr.x = (w1 * iv.x + w2 * fsT[(kb + q * 4 + 0) * 32 + r]) * inv;
        rr.y = (w1 * iv.y + w2 * fsT[(kb + q * 4 + 1) * 32 + r]) * inv;
        rr.z = (w1 * iv.z + w2 * fsT[(kb + q * 4 + 2) * 32 + r]) * inv;
        rr.w = (w1 * iv.w + w2 * fsT[(kb + q * 4 + 3) * 32 + r]) * inv;
        op[q] = rr;
    }
}

// ---------------- launch ----------------
extern "C" void kernel_launch(void* const* d_in, const int* in_sizes, int n_in,
                              void* d_out, int out_size) {
    int off = (n_in >= 11) ? 1 : 0;
    const float* x   = (const float*)d_in[0];
    const int*   Hm  = (const int*)d_in[1];
    const int*   adj = (const int*)d_in[2];
    const float* W   = (const float*)d_in[3 + off];
    const float* ah  = (const float*)d_in[4 + off];
    const float* ai  = (const float*)d_in[5 + off];
    const float* Wc1 = (const float*)d_in[6 + off];
    const float* bc1 = (const float*)d_in[7 + off];
    const float* wc2 = (const float*)d_in[8 + off];
    const float* bc2 = (const float*)d_in[9 + off];
    float* outp = (float*)d_out;

    k_front<<<585, 256>>>(x, W, ah, ai, adj, Hm);
    k_mid<<<2048 + 256, 256>>>();
    k_scoreA<<<512, 256>>>(Wc1, bc1, wc2, bc2);
    k_scoreBfin<<<T * N / 32, 256>>>(outp, Wc1, bc1, wc2, bc2);
}

// round 8
// speedup vs baseline: 1.1066x; 1.0628x over previous
#include <cuda_runtime.h>
#include <math.h>

#define T 32
#define N 512
#define E 64
#define F 64
#define HD 64
#define SLOPE 0.2f

// ---------------- device scratch ----------------
__device__ float g_h[T * N * HD];       // 4 MB
__device__ float g_shyp[T * N];
__device__ float g_sind[T * N];
__device__ float g_emax[T * E];
__device__ float g_einv[T * E];
__device__ float g_ind[T * N * HD];     // 4 MB
__device__ int   g_adj_cnt[N];
__device__ int   g_adj_nbr[N * N];
__device__ int   g_ne_cnt[N];
__device__ int   g_ne_off[N];
__device__ int   g_ne_lst[N * E];
__device__ int   g_en_cnt[E];
__device__ int   g_en_lst[E * N];
__device__ int   g_wl_n[N * E];
__device__ int   g_wl_e[N * E];
__device__ int   g_nnz;
__device__ int   g_Mhyp;
__device__ int   g_Mtot;
__device__ float g_zall[T * N * E + T * N];

// fast math: tolerance is 1e-3, __expf rel err ~1e-6
__device__ __forceinline__ float fexp(float v) { return __expf(v); }
__device__ __forceinline__ float elu1(float v) { return v > 0.f ? v : __expf(v) - 1.0f; }

// ---------------- fused front: h-GEMM + all CSR builds + scan (block-specialized) ----------------
__global__ void __launch_bounds__(256) k_front(const float* __restrict__ x,
                                               const float* __restrict__ W,
                                               const float* __restrict__ ah,
                                               const float* __restrict__ ai,
                                               const int* __restrict__ adj,
                                               const int* __restrict__ Hm) {
    int b = blockIdx.x;
    int tid = threadIdx.x;
    int lane = tid & 31;
    int wrp = tid >> 5;

    if (b < 512) {
        __shared__ float xs[32][65];
        __shared__ float ws[64][65];
        int r0 = b * 32;

        for (int i = tid; i < 32 * 64; i += 256) {
            int r = i >> 6, c = i & 63;
            xs[r][c] = x[(r0 + r) * F + c];
        }
        for (int i = tid; i < 64 * 64; i += 256) {
            int r = i >> 6, c = i & 63;
            ws[r][c] = W[i];
        }
        __syncthreads();

        int ty = tid >> 4, tx = tid & 15;
        float acc[2][4] = {{0.f,0.f,0.f,0.f},{0.f,0.f,0.f,0.f}};
        #pragma unroll 8
        for (int k = 0; k < 64; k++) {
            float xr0 = xs[ty * 2 + 0][k];
            float xr1 = xs[ty * 2 + 1][k];
            float wv[4];
            #pragma unroll
            for (int j = 0; j < 4; j++) wv[j] = ws[k][tx * 4 + j];
            #pragma unroll
            for (int j = 0; j < 4; j++) {
                acc[0][j] = fmaf(xr0, wv[j], acc[0][j]);
                acc[1][j] = fmaf(xr1, wv[j], acc[1][j]);
            }
        }
        __syncthreads();
        #pragma unroll
        for (int i = 0; i < 2; i++) {
            int r = ty * 2 + i;
            #pragma unroll
            for (int j = 0; j < 4; j++) xs[r][tx * 4 + j] = acc[i][j];
            float4 v = make_float4(acc[i][0], acc[i][1], acc[i][2], acc[i][3]);
            *(float4*)&g_h[(r0 + r) * HD + tx * 4] = v;
        }
        __syncthreads();

        int row = tid >> 3, oct = tid & 7;
        float sh = 0.f, si = 0.f;
        #pragma unroll
        for (int k = 0; k < 8; k++) {
            float v = xs[row][oct * 8 + k];
            sh = fmaf(v, __ldg(&ah[oct * 8 + k]), sh);
            si = fmaf(v, __ldg(&ai[oct * 8 + k]), si);
        }
        #pragma unroll
        for (int o = 4; o > 0; o >>= 1) {
            sh += __shfl_xor_sync(0xffffffffu, sh, o);
            si += __shfl_xor_sync(0xffffffffu, si, o);
        }
        if (oct == 0) {
            g_shyp[r0 + row] = sh >= 0.f ? sh : SLOPE * sh;
            g_sind[r0 + row] = si >= 0.f ? si : SLOPE * si;
        }
    } else if (b < 576) {                      // adjacency CSR
        int i = (b - 512) * 8 + wrp;
        int cnt = 0;
        #pragma unroll
        for (int c = 0; c < N / 32; c++) {
            int j = c * 32 + lane;
            bool m = adj[i * N + j] != 0;
            unsigned bl = __ballot_sync(0xffffffffu, m);
            if (m) g_adj_nbr[i * N + cnt + __popc(bl & ((1u << lane) - 1u))] = j;
            cnt += __popc(bl);
        }
        if (lane == 0) g_adj_cnt[i] = cnt;
    } else if (b < 584) {                      // edge -> member nodes
        int e = (b - 576) * 8 + wrp;
        int cnt = 0;
        #pragma unroll
        for (int c = 0; c < N / 32; c++) {
            int n = c * 32 + lane;
            bool m = Hm[n * E + e] != 0;
            unsigned bl = __ballot_sync(0xffffffffu, m);
            if (m) g_en_lst[e * N + cnt + __popc(bl & ((1u << lane) - 1u))] = n;
            cnt += __popc(bl);
        }
        if (lane == 0) g_en_cnt[e] = cnt;
    } else {                                   // node->edge CSR + scan + worklist
        __shared__ int buf[256];
        int n0 = tid * 2, n1 = tid * 2 + 1;
        int c0 = 0, c1 = 0;
        #pragma unroll
        for (int e = 0; e < E; e++) {
            if (Hm[n0 * E + e] != 0) g_ne_lst[n0 * E + (c0++)] = e;
            if (Hm[n1 * E + e] != 0) g_ne_lst[n1 * E + (c1++)] = e;
        }
        g_ne_cnt[n0] = c0;
        g_ne_cnt[n1] = c1;
        buf[tid] = c0 + c1;
        __syncthreads();
        #pragma unroll
        for (int o = 1; o < 256; o <<= 1) {
            int add = (tid >= o) ? buf[tid - o] : 0;
            __syncthreads();
            buf[tid] += add;
            __syncthreads();
        }
        int S = buf[tid];
        int off0 = S - c0 - c1;
        int off1 = off0 + c0;
        g_ne_off[n0] = off0;
        g_ne_off[n1] = off1;
        if (tid == 255) {
            int nnz = S;
            g_nnz = nnz;
            g_Mhyp = T * nnz;
            g_Mtot = T * nnz + T * N;
        }
        for (int j = 0; j < c0; j++) {
            g_wl_n[off0 + j] = n0;
            g_wl_e[off0 + j] = g_ne_lst[n0 * E + j];
        }
        for (int j = 0; j < c1; j++) {
            g_wl_n[off1 + j] = n1;
            g_wl_e[off1 + j] = g_ne_lst[n1 * E + j];
        }
    }
}

// ---------------- fused: industry (warp-per-row, 8-wide MLP) + hyperedge stats ----------------
__global__ void __launch_bounds__(256) k_mid() {
    int b = blockIdx.x;
    int tid = threadIdx.x;
    int lane = tid & 31;
    int wrp = tid >> 5;
    if (b < 2048) {
        __shared__ float smw[8][512];
        int row = b * 8 + wrp;
        int t = row >> 9;
        int i = row & (N - 1);
        int deg = g_adj_cnt[i];
        const int* nbr = g_adj_nbr + i * N;
        const float* si = g_sind + t * N;

        float m = -3.0e38f;
        for (int k = lane; k < deg; k += 32) m = fmaxf(m, si[nbr[k]]);
        #pragma unroll
        for (int o = 16; o > 0; o >>= 1) m = fmaxf(m, __shfl_xor_sync(0xffffffffu, m, o));
        float s = 0.f;
        for (int k = lane; k < deg; k += 32) {
            float w = fexp(si[nbr[k]] - m);
            smw[wrp][k] = w;
            s += w;
        }
        #pragma unroll
        for (int o = 16; o > 0; o >>= 1) s += __shfl_xor_sync(0xffffffffu, s, o);
        float inv = 1.f / s;
        __syncwarp();

        const float* hb = g_h + t * N * HD;
        float2 ac[8];
        #pragma unroll
        for (int u = 0; u < 8; u++) ac[u] = make_float2(0.f, 0.f);
        int k = 0;
        for (; k + 8 <= deg; k += 8) {
            #pragma unroll
            for (int u = 0; u < 8; u++) {
                float w = smw[wrp][k + u];
                float2 hv = *(const float2*)&hb[nbr[k + u] * HD + lane * 2];
                ac[u].x = fmaf(w, hv.x, ac[u].x);
                ac[u].y = fmaf(w, hv.y, ac[u].y);
            }
        }
        for (; k < deg; k++) {
            float w = smw[wrp][k];
            float2 hv = *(const float2*)&hb[nbr[k] * HD + lane * 2];
            ac[0].x = fmaf(w, hv.x, ac[0].x);
            ac[0].y = fmaf(w, hv.y, ac[0].y);
        }
        float2 r;
        r.x = (((ac[0].x + ac[1].x) + (ac[2].x + ac[3].x)) +
               ((ac[4].x + ac[5].x) + (ac[6].x + ac[7].x))) * inv;
        r.y = (((ac[0].y + ac[1].y) + (ac[2].y + ac[3].y)) +
               ((ac[4].y + ac[5].y) + (ac[6].y + ac[7].y))) * inv;
        *(float2*)&g_ind[row * HD + lane * 2] = r;
    } else {
        int w = (b - 2048) * 8 + wrp;
        int t = w / E, e = w % E;
        int cnt = g_en_cnt[e];
        const int* lst = g_en_lst + e * N;
        const float* sh = g_shyp + t * N;
        float m = -3.0e38f;
        for (int i = lane; i < cnt; i += 32) m = fmaxf(m, sh[lst[i]]);
        #pragma unroll
        for (int o = 16; o > 0; o >>= 1) m = fmaxf(m, __shfl_xor_sync(0xffffffffu, m, o));
        float s = 0.f;
        for (int i = lane; i < cnt; i += 32) s += fexp(sh[lst[i]] - m);
        #pragma unroll
        for (int o = 16; o > 0; o >>= 1) s += __shfl_xor_sync(0xffffffffu, s, o);
        if (lane == 0) { g_emax[w] = m; g_einv[w] = 1.f / s; }
    }
}

// ---------------- phase A: 128-row tiles, 256 threads, 8x4 register tiles ----------------
__global__ void __launch_bounds__(256) k_scoreA(const float* __restrict__ Wc1g,
                                                const float* __restrict__ bc1g,
                                                const float* __restrict__ wc2g,
                                                const float* __restrict__ bc2g) {
    __shared__ float Ws[HD * HD];              // 16 KB
    __shared__ float fsT[HD * 128];            // 32 KB, [k][row]
    int tid = threadIdx.x;
    int tx = tid & 15, ty = tid >> 4;
    int r = tid & 127, half = tid >> 7;

    for (int i = tid; i < HD * HD; i += 256) Ws[i] = Wc1g[i];
    float bc1r[4], wc2r[4];
    #pragma unroll
    for (int j = 0; j < 4; j++) {
        bc1r[j] = __ldg(&bc1g[tx * 4 + j]);
        wc2r[j] = __ldg(&wc2g[tx * 4 + j]);
    }
    float bc2 = __ldg(&bc2g[0]);
    int Mtot = g_Mtot, Mhyp = g_Mhyp, nnz = g_nnz;
    int ntiles = (Mtot + 127) >> 7;

    for (int tile = blockIdx.x; tile < ntiles; tile += gridDim.x) {
        __syncthreads();
        int row = tile * 128 + r;
        int kb = half * 32;
        if (row < Mhyp) {
            int t = row / nnz;
            int idx = row - t * nnz;
            int n = g_wl_n[idx], e = g_wl_e[idx];
            float a = fexp(g_shyp[t * N + n] - g_emax[t * E + e]) * g_einv[t * E + e];
            const float4* hp = (const float4*)&g_h[(t * N + n) * HD + kb];
            #pragma unroll
            for (int q = 0; q < 8; q++) {
                float4 v = hp[q];
                fsT[(kb + q * 4 + 0) * 128 + r] = elu1(a * v.x);
                fsT[(kb + q * 4 + 1) * 128 + r] = elu1(a * v.y);
                fsT[(kb + q * 4 + 2) * 128 + r] = elu1(a * v.z);
                fsT[(kb + q * 4 + 3) * 128 + r] = elu1(a * v.w);
            }
        } else if (row < Mtot) {
            const float4* ip = (const float4*)&g_ind[(row - Mhyp) * HD + kb];
            #pragma unroll
            for (int q = 0; q < 8; q++) {
                float4 v = ip[q];
                fsT[(kb + q * 4 + 0) * 128 + r] = v.x;
                fsT[(kb + q * 4 + 1) * 128 + r] = v.y;
                fsT[(kb + q * 4 + 2) * 128 + r] = v.z;
                fsT[(kb + q * 4 + 3) * 128 + r] = v.w;
            }
        } else {
            #pragma unroll
            for (int q = 0; q < 32; q++) fsT[(kb + q) * 128 + r] = 0.f;
        }
        __syncthreads();

        float acc[8][4];
        #pragma unroll
        for (int i = 0; i < 8; i++)
            #pragma unroll
            for (int j = 0; j < 4; j++) acc[i][j] = 0.f;

        #pragma unroll 8
        for (int k = 0; k < HD; k++) {
            float4 f0 = *(const float4*)&fsT[k * 128 + ty * 8];
            float4 f1 = *(const float4*)&fsT[k * 128 + ty * 8 + 4];
            float4 w = *(const float4*)&Ws[k * HD + tx * 4];
            float fv[8] = {f0.x, f0.y, f0.z, f0.w, f1.x, f1.y, f1.z, f1.w};
            float wv[4] = {w.x, w.y, w.z, w.w};
            #pragma unroll
            for (int i = 0; i < 8; i++)
                #pragma unroll
                for (int j = 0; j < 4; j++)
                    acc[i][j] = fmaf(fv[i], wv[j], acc[i][j]);
        }

        int rb = tile * 128 + ty * 8;
        #pragma unroll
        for (int i = 0; i < 8; i++) {
            float p = 0.f;
            #pragma unroll
            for (int j = 0; j < 4; j++)
                p = fmaf(fmaxf(acc[i][j] + bc1r[j], 0.f), wc2r[j], p);
            p += __shfl_down_sync(0xffffffffu, p, 8, 16);
            p += __shfl_down_sync(0xffffffffu, p, 4, 16);
            p += __shfl_down_sync(0xffffffffu, p, 2, 16);
            p += __shfl_down_sync(0xffffffffu, p, 1, 16);
            if (tx == 0 && rb + i < Mtot) g_zall[rb + i] = p + bc2;
        }
    }
}

// ---------------- phase B: 32-row tiles (grid 512), y8 build 8 thr/row + score + combine ----------------
__global__ void __launch_bounds__(256) k_scoreBfin(float* __restrict__ out,
                                                   const float* __restrict__ Wc1g,
                                                   const float* __restrict__ bc1g,
                                                   const float* __restrict__ wc2g,
                                                   const float* __restrict__ bc2g) {
    __shared__ float Ws[HD * HD];              // 16 KB
    __shared__ float fsT[HD * 32];             // 8 KB, [k][row]
    __shared__ float zs[32];
    int tid = threadIdx.x;
    int tx = tid & 15, ty = tid >> 4;          // GEMM: 4 cols x 2 rows
    int r = tid & 31, dgrp = tid >> 5;         // fill/combine: 8 thr per row, 8 dims each

    for (int i = tid; i < HD * HD; i += 256) Ws[i] = Wc1g[i];
    float bc1r[4], wc2r[4];
    #pragma unroll
    for (int j = 0; j < 4; j++) {
        bc1r[j] = __ldg(&bc1g[tx * 4 + j]);
        wc2r[j] = __ldg(&wc2g[tx * 4 + j]);
    }
    float bc2 = __ldg(&bc2g[0]);
    int Mhyp = g_Mhyp, nnz = g_nnz;

    int row = blockIdx.x * 32 + r;             // (t,n)
    int t = row >> 9, n = row & (N - 1);
    int deg = g_ne_cnt[n];
    int off = g_ne_off[n];
    int kb = dgrp * 8;

    // phase 1: y8 for 8 dims of this row
    {
        float h8[8];
        const float4* hp = (const float4*)&g_h[row * HD + kb];
        float4 v0 = hp[0], v1 = hp[1];
        h8[0] = v0.x; h8[1] = v0.y; h8[2] = v0.z; h8[3] = v0.w;
        h8[4] = v1.x; h8[5] = v1.y; h8[6] = v1.z; h8[7] = v1.w;
        float shn = g_shyp[row];
        const float* zb = g_zall + t * nnz + off;
        const int* el = g_ne_lst + n * E;
        float M = -3.0e38f;
        for (int j = 0; j < deg; j++) M = fmaxf(M, zb[j]);
        float y[8];
        #pragma unroll
        for (int q = 0; q < 8; q++) y[q] = 0.f;
        float S = 0.f;
        for (int j = 0; j < deg; j++) {
            float w = fexp(zb[j] - M);
            S += w;
            int e = el[j];
            float a = fexp(shn - g_emax[t * E + e]) * g_einv[t * E + e];
            #pragma unroll
            for (int q = 0; q < 8; q++)
                y[q] = fmaf(w, elu1(a * h8[q]), y[q]);
        }
        float inv = 1.f / S;
        #pragma unroll
        for (int q = 0; q < 8; q++)
            fsT[(kb + q) * 32 + r] = y[q] * inv;
    }
    __syncthreads();

    // phase 2: GEMM 32x64 + z
    {
        float acc[2][4];
        #pragma unroll
        for (int i = 0; i < 2; i++)
            #pragma unroll
            for (int j = 0; j < 4; j++) acc[i][j] = 0.f;
        #pragma unroll 16
        for (int k = 0; k < HD; k++) {
            float2 f = *(const float2*)&fsT[k * 32 + ty * 2];
            float4 w = *(const float4*)&Ws[k * HD + tx * 4];
            float wv[4] = {w.x, w.y, w.z, w.w};
            #pragma unroll
            for (int j = 0; j < 4; j++) {
                acc[0][j] = fmaf(f.x, wv[j], acc[0][j]);
                acc[1][j] = fmaf(f.y, wv[j], acc[1][j]);
            }
        }
        #pragma unroll
        for (int i = 0; i < 2; i++) {
            float p = 0.f;
            #pragma unroll
            for (int j = 0; j < 4; j++)
                p = fmaf(fmaxf(acc[i][j] + bc1r[j], 0.f), wc2r[j], p);
            p += __shfl_down_sync(0xffffffffu, p, 8, 16);
            p += __shfl_down_sync(0xffffffffu, p, 4, 16);
            p += __shfl_down_sync(0xffffffffu, p, 2, 16);
            p += __shfl_down_sync(0xffffffffu, p, 1, 16);
            if (tx == 0) zs[ty * 2 + i] = p + bc2;
        }
    }
    __syncthreads();

    // phase 3: combine, 8 thr per row, 8 dims each
    float z2 = zs[r];
    float z1 = g_zall[Mhyp + row];
    float m2 = fmaxf(z1, z2);
    float w1 = fexp(z1 - m2), w2 = fexp(z2 - m2);
    float inv = 1.f / (w1 + w2);
    const float4* ip = (const float4*)&g_ind[row * HD + kb];
    float4* op = (float4*)&out[row * HD + kb];
    #pragma unroll
    for (int q = 0; q < 2; q++) {
        float4 iv = ip[q];
        float4 rr;
        rr.x = (w1 * iv.x + w2 * fsT[(kb + q * 4 + 0) * 32 + r]) * inv;
        rr.y = (w1 * iv.y + w2 * fsT[(kb + q * 4 + 1) * 32 + r]) * inv;
        rr.z = (w1 * iv.z + w2 * fsT[(kb + q * 4 + 2) * 32 + r]) * inv;
        rr.w = (w1 * iv.w + w2 * fsT[(kb + q * 4 + 3) * 32 + r]) * inv;
        op[q] = rr;
    }
}

// ---------------- launch ----------------
extern "C" void kernel_launch(void* const* d_in, const int* in_sizes, int n_in,
                              void* d_out, int out_size) {
    int off = (n_in >= 11) ? 1 : 0;
    const float* x   = (const float*)d_in[0];
    const int*   Hm  = (const int*)d_in[1];
    const int*   adj = (const int*)d_in[2];
    const float* W   = (const float*)d_in[3 + off];
    const float* ah  = (const float*)d_in[4 + off];
    const float* ai  = (const float*)d_in[5 + off];
    const float* Wc1 = (const float*)d_in[6 + off];
    const float* bc1 = (const float*)d_in[7 + off];
    const float* wc2 = (const float*)d_in[8 + off];
    const float* bc2 = (const float*)d_in[9 + off];
    float* outp = (float*)d_out;

    k_front<<<585, 256>>>(x, W, ah, ai, adj, Hm);
    k_mid<<<2048 + 256, 256>>>();
    k_scoreA<<<512, 256>>>(Wc1, bc1, wc2, bc2);
    k_scoreBfin<<<T * N / 32, 256>>>(outp, Wc1, bc1, wc2, bc2);
}